// round 9
// baseline (speedup 1.0000x reference)
#include <cuda_runtime.h>
#include <math.h>

// Problem constants
#define WE    300
#define RVLD  320
#define DE    256
#define NV    50000
#define ND    100000
#define NB    4096
#define NGW   10
#define NZ    10
#define KP    320
#define KHALF 160          // split-K half

#define BM 64
#define BN 64
#define BK 32
#define LDT 68             // padded k-major row stride

// ---- device scratch (zero-init at load; k_loss last block restores zeros) ----
__device__ float  d_rvT[NV * RVLD];        // 64 MB
__device__ float  d_rdT[ND * DE];          // 102 MB
__device__ float  d_normedT[NB * KP];      // 5 MB
__device__ float  d_projP[DE * KP];        // 0.3 MB
__device__ float  d_tpre2[2 * NB * DE];    // 8 MB  (split-K partials)
__device__ float  d_tpreT[NB * DE];        // 4 MB
__device__ float  d_projpart[64];
__device__ double d_sum[DE];
__device__ double d_sumsq[DE];
__device__ double d_rdsq;
__device__ double d_projsq;
__device__ double d_loss;
__device__ unsigned int d_count;
__device__ float  d_ca[DE];
__device__ float  d_cb[DE];

// packed f32x2 helpers (FFMA2 path — sm_103a)
#define PACKF2(out, lo, hi) \
    asm("mov.b64 %0, {%1, %2};" : "=l"(out) : "r"(__float_as_uint(lo)), "r"(__float_as_uint(hi)))
#define UNPACKF2(lo, hi, in) \
    do { unsigned int _l, _h; \
         asm("mov.b64 {%0, %1}, %2;" : "=r"(_l), "=r"(_h) : "l"(in)); \
         lo = __uint_as_float(_l); hi = __uint_as_float(_h); } while (0)
#define FFMA2(d, a, b, c) \
    asm("fma.rn.f32x2 %0, %1, %2, %3;" : "=l"(d) : "l"(a), "l"(b), "l"(c))

__device__ __forceinline__ float warp_sum(float v) {
    #pragma unroll
    for (int o = 16; o > 0; o >>= 1) v += __shfl_xor_sync(0xffffffffu, v, o);
    return v;
}

// ---- K1: transpose rd -> rdT, fused sum(rd^2); block(0,0) finalizes stats ----
__global__ __launch_bounds__(256) void k_rd_T(const float* __restrict__ rd,
                                              const float* __restrict__ beta) {
    if (blockIdx.x == 0 && blockIdx.y == 0) {
        int de = threadIdx.x;
        double s = d_sum[de], q = d_sumsq[de];
        double mean = s / NB;
        double var = (q - s * mean) / (NB - 1);   // ddof = 1
        if (var < 1e-30) var = 1e-30;
        double rs = 1.0 / sqrt(sqrt(var));        // 1/sqrt(std)
        d_ca[de] = (float)rs;
        d_cb[de] = (float)((double)beta[de] - mean * rs);
        if (de == 0) {
            double p = 0.0;
            for (int i = 0; i < 64; i++) p += (double)d_projpart[i];
            d_projsq = p;
        }
    }

    __shared__ float tile[64][65];
    int t = threadIdx.x;
    int x0 = blockIdx.x * 64;          // doc
    int y0 = blockIdx.y * 64;          // de
    int r = t >> 4;
    int c = (t & 15) << 2;
    float ss = 0.f;
    #pragma unroll
    for (int i = 0; i < 4; i++) {
        int de = r + 16 * i;
        int doc = x0 + c;
        if (doc < ND) {
            float4 v = *(const float4*)&rd[(size_t)(y0 + de) * ND + doc];
            tile[de][c] = v.x; tile[de][c + 1] = v.y;
            tile[de][c + 2] = v.z; tile[de][c + 3] = v.w;
            ss += v.x * v.x + v.y * v.y + v.z * v.z + v.w * v.w;
        }
    }
    __syncthreads();
    #pragma unroll
    for (int i = 0; i < 4; i++) {
        int dl = r + 16 * i;
        int doc = x0 + dl;
        if (doc < ND) {
            float4 o = make_float4(tile[c][dl], tile[c + 1][dl],
                                   tile[c + 2][dl], tile[c + 3][dl]);
            *(float4*)&d_rdT[(size_t)doc * DE + y0 + c] = o;
        }
    }
    ss = warp_sum(ss);
    __shared__ float red[8];
    if ((t & 31) == 0) red[t >> 5] = ss;
    __syncthreads();
    if (t == 0) {
        float s = 0.f;
        #pragma unroll
        for (int i = 0; i < 8; i++) s += red[i];
        atomicAdd(&d_rdsq, (double)s);
    }
}

// ---- K2: transpose rv -> rvT (zero-padded to 320) ----
__global__ __launch_bounds__(256) void k_rv_T(const float* __restrict__ rv) {
    __shared__ float tile[64][65];
    int t = threadIdx.x;
    int x0 = blockIdx.x * 64;          // v
    int y0 = blockIdx.y * 64;          // we
    int r = t >> 4;
    int c = (t & 15) << 2;
    #pragma unroll
    for (int i = 0; i < 4; i++) {
        int we = y0 + r + 16 * i;
        int x = x0 + c;
        if (x < NV) {
            float4 v = make_float4(0.f, 0.f, 0.f, 0.f);
            if (we < WE) v = *(const float4*)&rv[(size_t)we * NV + x];
            int de = r + 16 * i;
            tile[de][c] = v.x; tile[de][c + 1] = v.y;
            tile[de][c + 2] = v.z; tile[de][c + 3] = v.w;
        }
    }
    __syncthreads();
    #pragma unroll
    for (int i = 0; i < 4; i++) {
        int vl = r + 16 * i;
        int v = x0 + vl;
        if (v < NV) {
            float4 o = make_float4(tile[c][vl], tile[c + 1][vl],
                                   tile[c + 2][vl], tile[c + 3][vl]);
            *(float4*)&d_rvT[(size_t)v * RVLD + y0 + c] = o;
        }
    }
}

// ---- K3: pad proj into projP, per-block partial sum(proj^2) ----
__global__ __launch_bounds__(256) void k_proj_prep(const float* __restrict__ proj) {
    int idx = blockIdx.x * 256 + threadIdx.x;
    float ss = 0.f;
    #pragma unroll
    for (int i = 0; i < 5; i++) {
        int o = idx + i * 64 * 256;
        int de = o / KP, cc = o % KP;
        float v = 0.f;
        if (cc < WE) { v = proj[de * WE + cc]; ss += v * v; }
        d_projP[o] = v;
    }
    ss = warp_sum(ss);
    __shared__ float red[8];
    int t = threadIdx.x;
    if ((t & 31) == 0) red[t >> 5] = ss;
    __syncthreads();
    if (t == 0) {
        float s = 0.f;
        #pragma unroll
        for (int i = 0; i < 8; i++) s += red[i];
        d_projpart[blockIdx.x] = s;
    }
}

// ---- K4: gather+normalize, 2 warps per batch, float4 ----
__global__ __launch_bounds__(256) void k_gather(const int* __restrict__ word_ids) {
    int tid = threadIdx.x;
    int pw   = tid >> 6;
    int half = (tid >> 5) & 1;
    int w    = tid >> 5;
    int lane = tid & 31;
    int b = blockIdx.x * 4 + pw;

    int idv = 0;
    if (lane < NGW) idv = word_ids[b * NGW + lane];

    int c0 = half * 40 + lane;
    int c1 = c0 + 32;
    bool has1 = (lane < 8);

    float4 a0 = make_float4(0, 0, 0, 0), a1 = a0;
    #pragma unroll
    for (int g = 0; g < NGW; g++) {
        int id = __shfl_sync(0xffffffffu, idv, g);
        const float4* row = (const float4*)&d_rvT[(size_t)id * RVLD];
        float4 v0 = row[c0];
        a0.x += v0.x; a0.y += v0.y; a0.z += v0.z; a0.w += v0.w;
        if (has1) {
            float4 v1 = row[c1];
            a1.x += v1.x; a1.y += v1.y; a1.z += v1.z; a1.w += v1.w;
        }
    }
    float ss = a0.x * a0.x + a0.y * a0.y + a0.z * a0.z + a0.w * a0.w
             + a1.x * a1.x + a1.y * a1.y + a1.z * a1.z + a1.w * a1.w;
    ss = warp_sum(ss);
    __shared__ float pss[8];
    if (!lane) pss[w] = ss;
    __syncthreads();
    float rn = rsqrtf(pss[pw * 2] + pss[pw * 2 + 1]);

    float4* outp = (float4*)&d_normedT[(size_t)b * KP];
    a0.x *= rn; a0.y *= rn; a0.z *= rn; a0.w *= rn;
    outp[c0] = a0;
    if (has1) {
        a1.x *= rn; a1.y *= rn; a1.z *= rn; a1.w *= rn;
        outp[c1] = a1;
    }
}

// ---- K5: split-K GEMM (z = k-half); k-major smem + FFMA2; no fused stats ----
__global__ __launch_bounds__(256) void k_gemm() {
    __shared__ float Ask[BK][LDT];     // [k][m]
    __shared__ float Bsk[BK][LDT];     // [k][n]
    int tid = threadIdx.x;
    int tx = tid & 15, ty = tid >> 4;
    int b0 = blockIdx.x * BM;
    int d0 = blockIdx.y * BN;
    int kbase = blockIdx.z * KHALF;
    float* dst = d_tpre2 + (size_t)blockIdx.z * (NB * DE);

    unsigned long long acc2[4][2];
    #pragma unroll
    for (int i = 0; i < 4; i++)
        #pragma unroll
        for (int jp = 0; jp < 2; jp++) acc2[i][jp] = 0ull;

    for (int k0 = kbase; k0 < kbase + KHALF; k0 += BK) {
        #pragma unroll
        for (int l = 0; l < 2; l++) {
            int f = tid + l * 256;
            int r = f >> 3;
            int c = (f & 7) << 2;
            float4 va = *(const float4*)&d_normedT[(size_t)(b0 + r) * KP + k0 + c];
            Ask[c + 0][r] = va.x; Ask[c + 1][r] = va.y;
            Ask[c + 2][r] = va.z; Ask[c + 3][r] = va.w;
            float4 vb = *(const float4*)&d_projP[(size_t)(d0 + r) * KP + k0 + c];
            Bsk[c + 0][r] = vb.x; Bsk[c + 1][r] = vb.y;
            Bsk[c + 2][r] = vb.z; Bsk[c + 3][r] = vb.w;
        }
        __syncthreads();
        #pragma unroll
        for (int k = 0; k < BK; k++) {
            float4 a4 = *(const float4*)&Ask[k][ty * 4];
            float4 b4 = *(const float4*)&Bsk[k][tx * 4];
            unsigned long long bp0, bp1;
            PACKF2(bp0, b4.x, b4.y);
            PACKF2(bp1, b4.z, b4.w);
            unsigned long long ad0, ad1, ad2, ad3;
            PACKF2(ad0, a4.x, a4.x);
            PACKF2(ad1, a4.y, a4.y);
            PACKF2(ad2, a4.z, a4.z);
            PACKF2(ad3, a4.w, a4.w);
            FFMA2(acc2[0][0], ad0, bp0, acc2[0][0]);
            FFMA2(acc2[0][1], ad0, bp1, acc2[0][1]);
            FFMA2(acc2[1][0], ad1, bp0, acc2[1][0]);
            FFMA2(acc2[1][1], ad1, bp1, acc2[1][1]);
            FFMA2(acc2[2][0], ad2, bp0, acc2[2][0]);
            FFMA2(acc2[2][1], ad2, bp1, acc2[2][1]);
            FFMA2(acc2[3][0], ad3, bp0, acc2[3][0]);
            FFMA2(acc2[3][1], ad3, bp1, acc2[3][1]);
        }
        __syncthreads();
    }

    #pragma unroll
    for (int i = 0; i < 4; i++) {
        float a0, a1, a2, a3;
        UNPACKF2(a0, a1, acc2[i][0]);
        UNPACKF2(a2, a3, acc2[i][1]);
        float4 o = make_float4(a0, a1, a2, a3);
        *(float4*)&dst[(size_t)(b0 + ty * 4 + i) * DE + d0 + tx * 4] = o;
    }
}

// ---- K5b: combine split-K halves -> t_pre; per-de Σ/Σ² ----
__global__ __launch_bounds__(256) void k_tstats() {
    int de = threadIdx.x;
    int r0 = blockIdx.x * 32;
    float s = 0.f, q = 0.f;
    #pragma unroll 4
    for (int i = 0; i < 32; i++) {
        size_t off = (size_t)(r0 + i) * DE + de;
        float v = d_tpre2[off] + d_tpre2[(size_t)NB * DE + off];
        d_tpreT[off] = v;
        s += v; q += v * v;
    }
    atomicAdd(&d_sum[de], (double)s);
    atomicAdd(&d_sumsq[de], (double)q);
}

// ---- K6: loss; last block finalizes output and re-zeros accumulators ----
__global__ __launch_bounds__(256) void k_loss(const int* __restrict__ doc_ids,
                                              const int* __restrict__ neg_ids,
                                              float* __restrict__ out) {
    int b = blockIdx.x, tid = threadIdx.x;
    int w = tid >> 5, lane = tid & 31;
    __shared__ float ts[DE];
    __shared__ float dots[11];
    __shared__ int   ids[11];
    if (tid < 11) ids[tid] = (tid == 0) ? doc_ids[b] : neg_ids[b * NZ + tid - 1];
    {
        float t = d_tpreT[(size_t)b * DE + tid] * d_ca[tid] + d_cb[tid];
        ts[tid] = fminf(1.f, fmaxf(-1.f, t));
    }
    __syncthreads();

    const float4* tt = (const float4*)ts;
    float4 t0 = tt[lane], t1 = tt[lane + 32];

    {
        int id = ids[w];
        const float4* rr = (const float4*)&d_rdT[(size_t)id * DE];
        float4 r0 = rr[lane], r1 = rr[lane + 32];
        float v = t0.x * r0.x + t0.y * r0.y + t0.z * r0.z + t0.w * r0.w
                + t1.x * r1.x + t1.y * r1.y + t1.z * r1.z + t1.w * r1.w;
        v = warp_sum(v);
        if (!lane) dots[w] = v;
    }
    if (w >= 5) {
        int id = ids[w + 3];
        const float4* rr = (const float4*)&d_rdT[(size_t)id * DE];
        float4 r0 = rr[lane], r1 = rr[lane + 32];
        float v = t0.x * r0.x + t0.y * r0.y + t0.z * r0.z + t0.w * r0.w
                + t1.x * r1.x + t1.y * r1.y + t1.z * r1.z + t1.w * r1.w;
        v = warp_sum(v);
        if (!lane) dots[w + 3] = v;
    }
    __syncthreads();
    if (tid == 0) {
        float p  = fminf(1.f / (1.f + expf(-dots[0])), 0.999f);
        float lp = 10.f * logf(p);
        float nsl = 0.f;
        #pragma unroll
        for (int z = 1; z <= NZ; z++) {
            float pn = fminf(1.f / (1.f + expf(-dots[z])), 0.999f);
            nsl += logf(fmaxf(1.f - pn, 0.01f));
        }
        atomicAdd(&d_loss, (double)(0.55f * (lp + nsl)));
        __threadfence();
        unsigned int r = atomicAdd(&d_count, 1u);
        if (r == NB - 1) {
            double total = atomicAdd(&d_loss, 0.0);
            out[0] = (float)(total / NB + (0.01 / (2.0 * NB)) * (d_rdsq + d_projsq));
            for (int i = 0; i < DE; i++) { d_sum[i] = 0.0; d_sumsq[i] = 0.0; }
            d_loss = 0.0;
            d_rdsq = 0.0;
            __threadfence();
            d_count = 0u;
        }
    }
}

extern "C" void kernel_launch(void* const* d_in, const int* in_sizes, int n_in,
                              void* d_out, int out_size) {
    const float* rv       = (const float*)d_in[0];
    const float* rd       = (const float*)d_in[1];
    const float* proj     = (const float*)d_in[2];
    const float* beta     = (const float*)d_in[3];
    const int*   word_ids = (const int*)d_in[4];
    const int*   doc_ids  = (const int*)d_in[5];
    const int*   neg_ids  = (const int*)d_in[6];
    float* out = (float*)d_out;

    k_rv_T<<<dim3((NV + 63) / 64, 5), 256>>>(rv);        // rvT L2-hot for gather
    k_proj_prep<<<64, 256>>>(proj);
    k_gather<<<NB / 4, 256>>>(word_ids);
    k_gemm<<<dim3(NB / BM, DE / BN, 2), 256>>>();        // split-K=2 -> 512 blocks
    k_tstats<<<NB / 32, 256>>>();
    k_rd_T<<<dim3((ND + 63) / 64, DE / 64), 256>>>(rd, beta);  // + stats finalize
    k_loss<<<NB, 256>>>(doc_ids, neg_ids, out);
}

// round 10
// speedup vs baseline: 1.0306x; 1.0306x over previous
#include <cuda_runtime.h>
#include <math.h>

// Problem constants
#define WE    300
#define RVLD  320
#define DE    256
#define NV    50000
#define ND    100000
#define NB    4096
#define NGW   10
#define NZ    10
#define KP    320

#define BM 64
#define BN 64
#define BK 32
#define LDT 68             // padded k-major row stride

#define GEMM_BLOCKS 256    // 64 x 4 tile grid
#define RDT_BX 1563        // ceil(100000/64)

// ---- device scratch (zero-init at load; k_loss last block restores zeros) ----
__device__ float  d_rvT[NV * RVLD];        // 64 MB
__device__ float  d_rdT[ND * DE];          // 102 MB
__device__ float  d_normedT[NB * KP];      // 5 MB
__device__ float  d_projP[DE * KP];        // 0.3 MB
__device__ float  d_tpreT[NB * DE];        // 4 MB
__device__ float  d_projpart[64];
__device__ double d_sum[DE];
__device__ double d_sumsq[DE];
__device__ double d_rdsq;
__device__ double d_projsq;
__device__ double d_loss;
__device__ unsigned int d_count;
__device__ float  d_ca[DE];
__device__ float  d_cb[DE];

// packed f32x2 helpers (FFMA2 path — sm_103a)
#define PACKF2(out, lo, hi) \
    asm("mov.b64 %0, {%1, %2};" : "=l"(out) : "r"(__float_as_uint(lo)), "r"(__float_as_uint(hi)))
#define UNPACKF2(lo, hi, in) \
    do { unsigned int _l, _h; \
         asm("mov.b64 {%0, %1}, %2;" : "=r"(_l), "=r"(_h) : "l"(in)); \
         lo = __uint_as_float(_l); hi = __uint_as_float(_h); } while (0)
#define FFMA2(d, a, b, c) \
    asm("fma.rn.f32x2 %0, %1, %2, %3;" : "=l"(d) : "l"(a), "l"(b), "l"(c))

__device__ __forceinline__ float warp_sum(float v) {
    #pragma unroll
    for (int o = 16; o > 0; o >>= 1) v += __shfl_xor_sync(0xffffffffu, v, o);
    return v;
}

// shared-memory alias for the fused mid kernel
union __align__(16) SmemU {
    struct { float Ask[BK][LDT]; float Bsk[BK][LDT]; } g;   // gemm tiles  (17408 B)
    struct { float tile[64][65]; float red[8]; } t;          // transpose   (16672 B)
    struct { float stS[16][64]; float stQ[16][64]; } s;      // gemm stats  (8192 B)
};

// ---- K2: transpose rv -> rvT (zero-padded to 320) ----
__global__ __launch_bounds__(256) void k_rv_T(const float* __restrict__ rv) {
    __shared__ float tile[64][65];
    int t = threadIdx.x;
    int x0 = blockIdx.x * 64;          // v
    int y0 = blockIdx.y * 64;          // we
    int r = t >> 4;
    int c = (t & 15) << 2;
    #pragma unroll
    for (int i = 0; i < 4; i++) {
        int we = y0 + r + 16 * i;
        int x = x0 + c;
        if (x < NV) {
            float4 v = make_float4(0.f, 0.f, 0.f, 0.f);
            if (we < WE) v = *(const float4*)&rv[(size_t)we * NV + x];
            int de = r + 16 * i;
            tile[de][c] = v.x; tile[de][c + 1] = v.y;
            tile[de][c + 2] = v.z; tile[de][c + 3] = v.w;
        }
    }
    __syncthreads();
    #pragma unroll
    for (int i = 0; i < 4; i++) {
        int vl = r + 16 * i;
        int v = x0 + vl;
        if (v < NV) {
            float4 o = make_float4(tile[c][vl], tile[c + 1][vl],
                                   tile[c + 2][vl], tile[c + 3][vl]);
            *(float4*)&d_rvT[(size_t)v * RVLD + y0 + c] = o;
        }
    }
}

// ---- K3: pad proj into projP, per-block partial sum(proj^2) ----
__global__ __launch_bounds__(256) void k_proj_prep(const float* __restrict__ proj) {
    int idx = blockIdx.x * 256 + threadIdx.x;
    float ss = 0.f;
    #pragma unroll
    for (int i = 0; i < 5; i++) {
        int o = idx + i * 64 * 256;
        int de = o / KP, cc = o % KP;
        float v = 0.f;
        if (cc < WE) { v = proj[de * WE + cc]; ss += v * v; }
        d_projP[o] = v;
    }
    ss = warp_sum(ss);
    __shared__ float red[8];
    int t = threadIdx.x;
    if ((t & 31) == 0) red[t >> 5] = ss;
    __syncthreads();
    if (t == 0) {
        float s = 0.f;
        #pragma unroll
        for (int i = 0; i < 8; i++) s += red[i];
        d_projpart[blockIdx.x] = s;
    }
}

// ---- K4: gather+normalize, 2 warps per batch, float4 ----
__global__ __launch_bounds__(256) void k_gather(const int* __restrict__ word_ids) {
    int tid = threadIdx.x;
    int pw   = tid >> 6;
    int half = (tid >> 5) & 1;
    int w    = tid >> 5;
    int lane = tid & 31;
    int b = blockIdx.x * 4 + pw;

    int idv = 0;
    if (lane < NGW) idv = word_ids[b * NGW + lane];

    int c0 = half * 40 + lane;
    int c1 = c0 + 32;
    bool has1 = (lane < 8);

    float4 a0 = make_float4(0, 0, 0, 0), a1 = a0;
    #pragma unroll
    for (int g = 0; g < NGW; g++) {
        int id = __shfl_sync(0xffffffffu, idv, g);
        const float4* row = (const float4*)&d_rvT[(size_t)id * RVLD];
        float4 v0 = row[c0];
        a0.x += v0.x; a0.y += v0.y; a0.z += v0.z; a0.w += v0.w;
        if (has1) {
            float4 v1 = row[c1];
            a1.x += v1.x; a1.y += v1.y; a1.z += v1.z; a1.w += v1.w;
        }
    }
    float ss = a0.x * a0.x + a0.y * a0.y + a0.z * a0.z + a0.w * a0.w
             + a1.x * a1.x + a1.y * a1.y + a1.z * a1.z + a1.w * a1.w;
    ss = warp_sum(ss);
    __shared__ float pss[8];
    if (!lane) pss[w] = ss;
    __syncthreads();
    float rn = rsqrtf(pss[pw * 2] + pss[pw * 2 + 1]);

    float4* outp = (float4*)&d_normedT[(size_t)b * KP];
    a0.x *= rn; a0.y *= rn; a0.z *= rn; a0.w *= rn;
    outp[c0] = a0;
    if (has1) {
        a1.x *= rn; a1.y *= rn; a1.z *= rn; a1.w *= rn;
        outp[c1] = a1;
    }
}

// ---- K5: fused mid kernel — bid<256: GEMM tile; else: rd transpose tile ----
__global__ __launch_bounds__(256) void k_mid(const float* __restrict__ rd) {
    __shared__ SmemU u;
    int tid = threadIdx.x;

    if (blockIdx.x < GEMM_BLOCKS) {
        // ---------------- GEMM branch (64x4 tile grid) ----------------
        int gx = blockIdx.x & 63;
        int gy = blockIdx.x >> 6;
        int tx = tid & 15, ty = tid >> 4;
        int b0 = gx * BM;
        int d0 = gy * BN;

        unsigned long long acc2[4][2];
        #pragma unroll
        for (int i = 0; i < 4; i++)
            #pragma unroll
            for (int jp = 0; jp < 2; jp++) acc2[i][jp] = 0ull;

        for (int k0 = 0; k0 < KP; k0 += BK) {
            #pragma unroll
            for (int l = 0; l < 2; l++) {
                int f = tid + l * 256;
                int r = f >> 3;
                int c = (f & 7) << 2;
                float4 va = *(const float4*)&d_normedT[(size_t)(b0 + r) * KP + k0 + c];
                u.g.Ask[c + 0][r] = va.x; u.g.Ask[c + 1][r] = va.y;
                u.g.Ask[c + 2][r] = va.z; u.g.Ask[c + 3][r] = va.w;
                float4 vb = *(const float4*)&d_projP[(size_t)(d0 + r) * KP + k0 + c];
                u.g.Bsk[c + 0][r] = vb.x; u.g.Bsk[c + 1][r] = vb.y;
                u.g.Bsk[c + 2][r] = vb.z; u.g.Bsk[c + 3][r] = vb.w;
            }
            __syncthreads();
            #pragma unroll
            for (int k = 0; k < BK; k++) {
                float4 a4 = *(const float4*)&u.g.Ask[k][ty * 4];
                float4 b4 = *(const float4*)&u.g.Bsk[k][tx * 4];
                unsigned long long bp0, bp1;
                PACKF2(bp0, b4.x, b4.y);
                PACKF2(bp1, b4.z, b4.w);
                unsigned long long ad0, ad1, ad2, ad3;
                PACKF2(ad0, a4.x, a4.x);
                PACKF2(ad1, a4.y, a4.y);
                PACKF2(ad2, a4.z, a4.z);
                PACKF2(ad3, a4.w, a4.w);
                FFMA2(acc2[0][0], ad0, bp0, acc2[0][0]);
                FFMA2(acc2[0][1], ad0, bp1, acc2[0][1]);
                FFMA2(acc2[1][0], ad1, bp0, acc2[1][0]);
                FFMA2(acc2[1][1], ad1, bp1, acc2[1][1]);
                FFMA2(acc2[2][0], ad2, bp0, acc2[2][0]);
                FFMA2(acc2[2][1], ad2, bp1, acc2[2][1]);
                FFMA2(acc2[3][0], ad3, bp0, acc2[3][0]);
                FFMA2(acc2[3][1], ad3, bp1, acc2[3][1]);
            }
            __syncthreads();
        }

        float acc[4][4];
        #pragma unroll
        for (int i = 0; i < 4; i++) {
            UNPACKF2(acc[i][0], acc[i][1], acc2[i][0]);
            UNPACKF2(acc[i][2], acc[i][3], acc2[i][1]);
        }

        #pragma unroll
        for (int i = 0; i < 4; i++) {
            float4 o = make_float4(acc[i][0], acc[i][1], acc[i][2], acc[i][3]);
            *(float4*)&d_tpreT[(size_t)(b0 + ty * 4 + i) * DE + d0 + tx * 4] = o;
        }

        #pragma unroll
        for (int j = 0; j < 4; j++) {
            float s = 0.f, q = 0.f;
            #pragma unroll
            for (int i = 0; i < 4; i++) { s += acc[i][j]; q += acc[i][j] * acc[i][j]; }
            u.s.stS[ty][tx * 4 + j] = s;
            u.s.stQ[ty][tx * 4 + j] = q;
        }
        __syncthreads();
        if (tid < 64) {
            float s = 0.f, q = 0.f;
            #pragma unroll
            for (int r = 0; r < 16; r++) { s += u.s.stS[r][tid]; q += u.s.stQ[r][tid]; }
            atomicAdd(&d_sum[d0 + tid], (double)s);
            atomicAdd(&d_sumsq[d0 + tid], (double)q);
        }
    } else {
        // ---------------- rd transpose branch ----------------
        int rbid = blockIdx.x - GEMM_BLOCKS;
        int bx = rbid % RDT_BX;            // doc tile
        int by = rbid / RDT_BX;            // de tile (0..3)
        int x0 = bx * 64;                  // doc
        int y0 = by * 64;                  // de
        int r = tid >> 4;
        int c = (tid & 15) << 2;
        float ss = 0.f;
        #pragma unroll
        for (int i = 0; i < 4; i++) {
            int de = r + 16 * i;
            int doc = x0 + c;
            if (doc < ND) {
                float4 v = *(const float4*)&rd[(size_t)(y0 + de) * ND + doc];
                u.t.tile[de][c] = v.x; u.t.tile[de][c + 1] = v.y;
                u.t.tile[de][c + 2] = v.z; u.t.tile[de][c + 3] = v.w;
                ss += v.x * v.x + v.y * v.y + v.z * v.z + v.w * v.w;
            }
        }
        __syncthreads();
        #pragma unroll
        for (int i = 0; i < 4; i++) {
            int dl = r + 16 * i;
            int doc = x0 + dl;
            if (doc < ND) {
                float4 o = make_float4(u.t.tile[c][dl], u.t.tile[c + 1][dl],
                                       u.t.tile[c + 2][dl], u.t.tile[c + 3][dl]);
                *(float4*)&d_rdT[(size_t)doc * DE + y0 + c] = o;
            }
        }
        ss = warp_sum(ss);
        if ((tid & 31) == 0) u.t.red[tid >> 5] = ss;
        __syncthreads();
        if (tid == 0) {
            float s = 0.f;
            #pragma unroll
            for (int i = 0; i < 8; i++) s += u.t.red[i];
            atomicAdd(&d_rdsq, (double)s);
        }
    }
}

// ---- K6: finalize per-de affine (tiny; FP64 fine here) ----
__global__ void k_stats(const float* __restrict__ beta) {
    int de = threadIdx.x;
    double s = d_sum[de], q = d_sumsq[de];
    double mean = s / NB;
    double var = (q - s * mean) / (NB - 1);   // ddof = 1
    if (var < 1e-30) var = 1e-30;
    double rs = 1.0 / sqrt(sqrt(var));        // 1/sqrt(std)
    d_ca[de] = (float)rs;
    d_cb[de] = (float)((double)beta[de] - mean * rs);
    if (de == 0) {
        double p = 0.0;
        for (int i = 0; i < 64; i++) p += (double)d_projpart[i];
        d_projsq = p;
    }
}

// ---- K7: loss; last block finalizes output and re-zeros accumulators ----
__global__ __launch_bounds__(256) void k_loss(const int* __restrict__ doc_ids,
                                              const int* __restrict__ neg_ids,
                                              float* __restrict__ out) {
    int b = blockIdx.x, tid = threadIdx.x;
    int w = tid >> 5, lane = tid & 31;
    __shared__ float ts[DE];
    __shared__ float dots[11];
    __shared__ int   ids[11];
    if (tid < 11) ids[tid] = (tid == 0) ? doc_ids[b] : neg_ids[b * NZ + tid - 1];
    {
        float t = d_tpreT[(size_t)b * DE + tid] * d_ca[tid] + d_cb[tid];
        ts[tid] = fminf(1.f, fmaxf(-1.f, t));
    }
    __syncthreads();

    const float4* tt = (const float4*)ts;
    float4 t0 = tt[lane], t1 = tt[lane + 32];

    {
        int id = ids[w];
        const float4* rr = (const float4*)&d_rdT[(size_t)id * DE];
        float4 r0 = rr[lane], r1 = rr[lane + 32];
        float v = t0.x * r0.x + t0.y * r0.y + t0.z * r0.z + t0.w * r0.w
                + t1.x * r1.x + t1.y * r1.y + t1.z * r1.z + t1.w * r1.w;
        v = warp_sum(v);
        if (!lane) dots[w] = v;
    }
    if (w >= 5) {
        int id = ids[w + 3];
        const float4* rr = (const float4*)&d_rdT[(size_t)id * DE];
        float4 r0 = rr[lane], r1 = rr[lane + 32];
        float v = t0.x * r0.x + t0.y * r0.y + t0.z * r0.z + t0.w * r0.w
                + t1.x * r1.x + t1.y * r1.y + t1.z * r1.z + t1.w * r1.w;
        v = warp_sum(v);
        if (!lane) dots[w + 3] = v;
    }
    __syncthreads();
    if (tid == 0) {
        float p  = fminf(1.f / (1.f + expf(-dots[0])), 0.999f);
        float lp = 10.f * logf(p);
        float nsl = 0.f;
        #pragma unroll
        for (int z = 1; z <= NZ; z++) {
            float pn = fminf(1.f / (1.f + expf(-dots[z])), 0.999f);
            nsl += logf(fmaxf(1.f - pn, 0.01f));
        }
        atomicAdd(&d_loss, (double)(0.55f * (lp + nsl)));
        __threadfence();
        unsigned int r = atomicAdd(&d_count, 1u);
        if (r == NB - 1) {
            double total = atomicAdd(&d_loss, 0.0);
            out[0] = (float)(total / NB + (0.01 / (2.0 * NB)) * (d_rdsq + d_projsq));
            for (int i = 0; i < DE; i++) { d_sum[i] = 0.0; d_sumsq[i] = 0.0; }
            d_loss = 0.0;
            d_rdsq = 0.0;
            __threadfence();
            d_count = 0u;
        }
    }
}

extern "C" void kernel_launch(void* const* d_in, const int* in_sizes, int n_in,
                              void* d_out, int out_size) {
    const float* rv       = (const float*)d_in[0];
    const float* rd       = (const float*)d_in[1];
    const float* proj     = (const float*)d_in[2];
    const float* beta     = (const float*)d_in[3];
    const int*   word_ids = (const int*)d_in[4];
    const int*   doc_ids  = (const int*)d_in[5];
    const int*   neg_ids  = (const int*)d_in[6];
    float* out = (float*)d_out;

    k_rv_T<<<dim3((NV + 63) / 64, 5), 256>>>(rv);
    k_proj_prep<<<64, 256>>>(proj);
    k_gather<<<NB / 4, 256>>>(word_ids);
    k_mid<<<GEMM_BLOCKS + RDT_BX * 4, 256>>>(rd);    // gemm + rd_T fused
    k_stats<<<1, DE>>>(beta);
    k_loss<<<NB, 256>>>(doc_ids, neg_ids, out);
}

// round 12
// speedup vs baseline: 1.1875x; 1.1523x over previous
#include <cuda_runtime.h>
#include <math.h>
#include <mma.h>

using namespace nvcuda;

// Problem constants
#define WE    300
#define RVLD  320
#define DE    256
#define NV    50000
#define ND    100000
#define NB    4096
#define NGW   10
#define NZ    10
#define KP    320

#define BM 64
#define BN 64
#define LDA 36             // smem row stride for A/B tiles (k-extent 32 + pad)
#define LDTOUT 68          // smem row stride for output tile

// ---- device scratch (zero-init at load; k_loss last block restores zeros) ----
__device__ float  d_rvT[NV * RVLD];        // 64 MB
__device__ float  d_rdT[ND * DE];          // 102 MB
__device__ float  d_normedT[NB * KP];      // 5 MB
__device__ float  d_projP[DE * KP];        // 0.3 MB
__device__ float  d_tpreT[NB * DE];        // 4 MB
__device__ float  d_projpart[64];
__device__ double d_sum[DE];
__device__ double d_sumsq[DE];
__device__ double d_rdsq;
__device__ double d_projsq;
__device__ double d_loss;
__device__ unsigned int d_count;
__device__ float  d_ca[DE];
__device__ float  d_cb[DE];

__device__ __forceinline__ float warp_sum(float v) {
    #pragma unroll
    for (int o = 16; o > 0; o >>= 1) v += __shfl_xor_sync(0xffffffffu, v, o);
    return v;
}

// ---- K1: transpose rd -> rdT, fused sum(rd^2); block(0,0) finalizes stats ----
__global__ __launch_bounds__(256) void k_rd_T(const float* __restrict__ rd,
                                              const float* __restrict__ beta) {
    if (blockIdx.x == 0 && blockIdx.y == 0) {
        int de = threadIdx.x;
        double s = d_sum[de], q = d_sumsq[de];
        double mean = s / NB;
        double var = (q - s * mean) / (NB - 1);   // ddof = 1
        if (var < 1e-30) var = 1e-30;
        double rs = 1.0 / sqrt(sqrt(var));        // 1/sqrt(std)
        d_ca[de] = (float)rs;
        d_cb[de] = (float)((double)beta[de] - mean * rs);
        if (de == 0) {
            double p = 0.0;
            for (int i = 0; i < 64; i++) p += (double)d_projpart[i];
            d_projsq = p;
        }
    }

    __shared__ float tile[64][65];
    int t = threadIdx.x;
    int x0 = blockIdx.x * 64;          // doc
    int y0 = blockIdx.y * 64;          // de
    int r = t >> 4;
    int c = (t & 15) << 2;
    float ss = 0.f;
    #pragma unroll
    for (int i = 0; i < 4; i++) {
        int de = r + 16 * i;
        int doc = x0 + c;
        if (doc < ND) {
            float4 v = *(const float4*)&rd[(size_t)(y0 + de) * ND + doc];
            tile[de][c] = v.x; tile[de][c + 1] = v.y;
            tile[de][c + 2] = v.z; tile[de][c + 3] = v.w;
            ss += v.x * v.x + v.y * v.y + v.z * v.z + v.w * v.w;
        }
    }
    __syncthreads();
    #pragma unroll
    for (int i = 0; i < 4; i++) {
        int dl = r + 16 * i;
        int doc = x0 + dl;
        if (doc < ND) {
            float4 o = make_float4(tile[c][dl], tile[c + 1][dl],
                                   tile[c + 2][dl], tile[c + 3][dl]);
            *(float4*)&d_rdT[(size_t)doc * DE + y0 + c] = o;
        }
    }
    ss = warp_sum(ss);
    __shared__ float red[8];
    if ((t & 31) == 0) red[t >> 5] = ss;
    __syncthreads();
    if (t == 0) {
        float s = 0.f;
        #pragma unroll
        for (int i = 0; i < 8; i++) s += red[i];
        atomicAdd(&d_rdsq, (double)s);
    }
}

// ---- K2: transpose rv -> rvT (zero-padded to 320) ----
__global__ __launch_bounds__(256) void k_rv_T(const float* __restrict__ rv) {
    __shared__ float tile[64][65];
    int t = threadIdx.x;
    int x0 = blockIdx.x * 64;          // v
    int y0 = blockIdx.y * 64;          // we
    int r = t >> 4;
    int c = (t & 15) << 2;
    #pragma unroll
    for (int i = 0; i < 4; i++) {
        int we = y0 + r + 16 * i;
        int x = x0 + c;
        if (x < NV) {
            float4 v = make_float4(0.f, 0.f, 0.f, 0.f);
            if (we < WE) v = *(const float4*)&rv[(size_t)we * NV + x];
            int de = r + 16 * i;
            tile[de][c] = v.x; tile[de][c + 1] = v.y;
            tile[de][c + 2] = v.z; tile[de][c + 3] = v.w;
        }
    }
    __syncthreads();
    #pragma unroll
    for (int i = 0; i < 4; i++) {
        int vl = r + 16 * i;
        int v = x0 + vl;
        if (v < NV) {
            float4 o = make_float4(tile[c][vl], tile[c + 1][vl],
                                   tile[c + 2][vl], tile[c + 3][vl]);
            *(float4*)&d_rvT[(size_t)v * RVLD + y0 + c] = o;
        }
    }
}

// ---- K3: pad proj into projP, per-block partial sum(proj^2) ----
__global__ __launch_bounds__(256) void k_proj_prep(const float* __restrict__ proj) {
    int idx = blockIdx.x * 256 + threadIdx.x;
    float ss = 0.f;
    #pragma unroll
    for (int i = 0; i < 5; i++) {
        int o = idx + i * 64 * 256;
        int de = o / KP, cc = o % KP;
        float v = 0.f;
        if (cc < WE) { v = proj[de * WE + cc]; ss += v * v; }
        d_projP[o] = v;
    }
    ss = warp_sum(ss);
    __shared__ float red[8];
    int t = threadIdx.x;
    if ((t & 31) == 0) red[t >> 5] = ss;
    __syncthreads();
    if (t == 0) {
        float s = 0.f;
        #pragma unroll
        for (int i = 0; i < 8; i++) s += red[i];
        d_projpart[blockIdx.x] = s;
    }
}

// ---- K4: gather+normalize, 2 warps per batch, float4 ----
__global__ __launch_bounds__(256) void k_gather(const int* __restrict__ word_ids) {
    int tid = threadIdx.x;
    int pw   = tid >> 6;
    int half = (tid >> 5) & 1;
    int w    = tid >> 5;
    int lane = tid & 31;
    int b = blockIdx.x * 4 + pw;

    int idv = 0;
    if (lane < NGW) idv = word_ids[b * NGW + lane];

    int c0 = half * 40 + lane;
    int c1 = c0 + 32;
    bool has1 = (lane < 8);

    float4 a0 = make_float4(0, 0, 0, 0), a1 = a0;
    #pragma unroll
    for (int g = 0; g < NGW; g++) {
        int id = __shfl_sync(0xffffffffu, idv, g);
        const float4* row = (const float4*)&d_rvT[(size_t)id * RVLD];
        float4 v0 = row[c0];
        a0.x += v0.x; a0.y += v0.y; a0.z += v0.z; a0.w += v0.w;
        if (has1) {
            float4 v1 = row[c1];
            a1.x += v1.x; a1.y += v1.y; a1.z += v1.z; a1.w += v1.w;
        }
    }
    float ss = a0.x * a0.x + a0.y * a0.y + a0.z * a0.z + a0.w * a0.w
             + a1.x * a1.x + a1.y * a1.y + a1.z * a1.z + a1.w * a1.w;
    ss = warp_sum(ss);
    __shared__ float pss[8];
    if (!lane) pss[w] = ss;
    __syncthreads();
    float rn = rsqrtf(pss[pw * 2] + pss[pw * 2 + 1]);

    float4* outp = (float4*)&d_normedT[(size_t)b * KP];
    a0.x *= rn; a0.y *= rn; a0.z *= rn; a0.w *= rn;
    outp[c0] = a0;
    if (has1) {
        a1.x *= rn; a1.y *= rn; a1.z *= rn; a1.w *= rn;
        outp[c1] = a1;
    }
}

// ---- K5: tf32 wmma GEMM 4096x256x320, fused per-de Σ/Σ² ----
// 8 warps as 4(m) x 2(n); each warp: one 16-row m-tile, two 16-col n-tiles.
union __align__(16) GSmem {
    struct { float As[BM][LDA]; float Bs[BN][LDA]; } in;   // 18432 B
    struct { float T[BM][LDTOUT]; } outp;                  // 17408 B
};

__global__ __launch_bounds__(256) void k_gemm() {
    __shared__ GSmem u;
    __shared__ float sS[4][64];
    __shared__ float sQ[4][64];

    int tid = threadIdx.x;
    int wid = tid >> 5;
    int wm = wid & 3;              // m-tile 0..3
    int wn = wid >> 2;             // n-half 0..1
    int b0 = blockIdx.x * BM;
    int d0 = blockIdx.y * BN;

    wmma::fragment<wmma::accumulator, 16, 16, 8, float> acc[2];
    wmma::fill_fragment(acc[0], 0.f);
    wmma::fill_fragment(acc[1], 0.f);

    for (int k0 = 0; k0 < KP; k0 += 32) {
        #pragma unroll
        for (int l = 0; l < 2; l++) {
            int f = tid + l * 256;         // 0..511
            int r = f >> 3;                // 0..63
            int c = (f & 7) << 2;          // 0..28
            *(float4*)&u.in.As[r][c] = *(const float4*)&d_normedT[(size_t)(b0 + r) * KP + k0 + c];
            *(float4*)&u.in.Bs[r][c] = *(const float4*)&d_projP[(size_t)(d0 + r) * KP + k0 + c];
        }
        __syncthreads();
        #pragma unroll
        for (int kk = 0; kk < 32; kk += 8) {
            wmma::fragment<wmma::matrix_a, 16, 16, 8, wmma::precision::tf32, wmma::row_major> af;
            wmma::load_matrix_sync(af, &u.in.As[wm * 16][kk], LDA);
            #pragma unroll
            for (int i = 0; i < af.num_elements; i++) af.x[i] = wmma::__float_to_tf32(af.x[i]);
            #pragma unroll
            for (int j = 0; j < 2; j++) {
                wmma::fragment<wmma::matrix_b, 16, 16, 8, wmma::precision::tf32, wmma::col_major> bf;
                wmma::load_matrix_sync(bf, &u.in.Bs[wn * 32 + j * 16][kk], LDA);
                #pragma unroll
                for (int i = 0; i < bf.num_elements; i++) bf.x[i] = wmma::__float_to_tf32(bf.x[i]);
                wmma::mma_sync(acc[j], af, bf, acc[j]);
            }
        }
        __syncthreads();
    }

    // stage result tile in smem
    #pragma unroll
    for (int j = 0; j < 2; j++)
        wmma::store_matrix_sync(&u.outp.T[wm * 16][wn * 32 + j * 16], acc[j],
                                LDTOUT, wmma::mem_row_major);
    __syncthreads();

    // coalesced global store: 4 float4 per thread
    {
        int rr = tid >> 4;                 // 0..15
        int cc = (tid & 15) << 2;          // 0..60
        #pragma unroll
        for (int i = 0; i < 4; i++) {
            int row = rr + i * 16;
            float4 o = make_float4(u.outp.T[row][cc], u.outp.T[row][cc + 1],
                                   u.outp.T[row][cc + 2], u.outp.T[row][cc + 3]);
            *(float4*)&d_tpreT[(size_t)(b0 + row) * DE + d0 + cc] = o;
        }
    }

    // per-column (de) sums over the 64 rows of this tile
    {
        int col = tid & 63;
        int q   = tid >> 6;                // 0..3 (16 rows each)
        float s = 0.f, qq = 0.f;
        #pragma unroll
        for (int i = 0; i < 16; i++) {
            float v = u.outp.T[q * 16 + i][col];
            s += v; qq += v * v;
        }
        sS[q][col] = s;
        sQ[q][col] = qq;
    }
    __syncthreads();
    if (tid < 64) {
        float s = sS[0][tid] + sS[1][tid] + sS[2][tid] + sS[3][tid];
        float q = sQ[0][tid] + sQ[1][tid] + sQ[2][tid] + sQ[3][tid];
        atomicAdd(&d_sum[d0 + tid], (double)s);
        atomicAdd(&d_sumsq[d0 + tid], (double)q);
    }
}

// ---- K6: loss; last block finalizes output and re-zeros accumulators ----
__global__ __launch_bounds__(256) void k_loss(const int* __restrict__ doc_ids,
                                              const int* __restrict__ neg_ids,
                                              float* __restrict__ out) {
    int b = blockIdx.x, tid = threadIdx.x;
    int w = tid >> 5, lane = tid & 31;
    __shared__ float ts[DE];
    __shared__ float dots[11];
    __shared__ int   ids[11];
    if (tid < 11) ids[tid] = (tid == 0) ? doc_ids[b] : neg_ids[b * NZ + tid - 1];
    {
        float t = d_tpreT[(size_t)b * DE + tid] * d_ca[tid] + d_cb[tid];
        ts[tid] = fminf(1.f, fmaxf(-1.f, t));
    }
    __syncthreads();

    const float4* tt = (const float4*)ts;
    float4 t0 = tt[lane], t1 = tt[lane + 32];

    {
        int id = ids[w];
        const float4* rr = (const float4*)&d_rdT[(size_t)id * DE];
        float4 r0 = rr[lane], r1 = rr[lane + 32];
        float v = t0.x * r0.x + t0.y * r0.y + t0.z * r0.z + t0.w * r0.w
                + t1.x * r1.x + t1.y * r1.y + t1.z * r1.z + t1.w * r1.w;
        v = warp_sum(v);
        if (!lane) dots[w] = v;
    }
    if (w >= 5) {
        int id = ids[w + 3];
        const float4* rr = (const float4*)&d_rdT[(size_t)id * DE];
        float4 r0 = rr[lane], r1 = rr[lane + 32];
        float v = t0.x * r0.x + t0.y * r0.y + t0.z * r0.z + t0.w * r0.w
                + t1.x * r1.x + t1.y * r1.y + t1.z * r1.z + t1.w * r1.w;
        v = warp_sum(v);
        if (!lane) dots[w + 3] = v;
    }
    __syncthreads();
    if (tid == 0) {
        float p  = fminf(1.f / (1.f + expf(-dots[0])), 0.999f);
        float lp = 10.f * logf(p);
        float nsl = 0.f;
        #pragma unroll
        for (int z = 1; z <= NZ; z++) {
            float pn = fminf(1.f / (1.f + expf(-dots[z])), 0.999f);
            nsl += logf(fmaxf(1.f - pn, 0.01f));
        }
        atomicAdd(&d_loss, (double)(0.55f * (lp + nsl)));
        __threadfence();
        unsigned int r = atomicAdd(&d_count, 1u);
        if (r == NB - 1) {
            double total = atomicAdd(&d_loss, 0.0);
            out[0] = (float)(total / NB + (0.01 / (2.0 * NB)) * (d_rdsq + d_projsq));
            for (int i = 0; i < DE; i++) { d_sum[i] = 0.0; d_sumsq[i] = 0.0; }
            d_loss = 0.0;
            d_rdsq = 0.0;
            __threadfence();
            d_count = 0u;
        }
    }
}

extern "C" void kernel_launch(void* const* d_in, const int* in_sizes, int n_in,
                              void* d_out, int out_size) {
    const float* rv       = (const float*)d_in[0];
    const float* rd       = (const float*)d_in[1];
    const float* proj     = (const float*)d_in[2];
    const float* beta     = (const float*)d_in[3];
    const int*   word_ids = (const int*)d_in[4];
    const int*   doc_ids  = (const int*)d_in[5];
    const int*   neg_ids  = (const int*)d_in[6];
    float* out = (float*)d_out;

    k_rv_T<<<dim3((NV + 63) / 64, 5), 256>>>(rv);        // rvT L2-hot for gather
    k_proj_prep<<<64, 256>>>(proj);
    k_gather<<<NB / 4, 256>>>(word_ids);
    k_gemm<<<dim3(NB / BM, DE / BN), 256>>>();
    k_rd_T<<<dim3((ND + 63) / 64, DE / 64), 256>>>(rd, beta);  // + stats finalize
    k_loss<<<NB, 256>>>(doc_ids, neg_ids, out);
}